// round 3
// baseline (speedup 1.0000x reference)
#include <cuda_runtime.h>
#include <cuda_bf16.h>

#define NCLS 54
#define RPB  192       // rows per block == threads per block
#define THREADS 192

// -log(1 - 53*0.001) = -log(0.947)
#define C0_TERM 0.05445614f

__device__ double g_acc;

__global__ void zero_acc_kernel() { g_acc = 0.0; }

__global__ void __launch_bounds__(THREADS)
importance_loss_kernel(const float* __restrict__ logits,
                       const int*   __restrict__ target,
                       const int*   __restrict__ mask,   // bool promoted to int32 by harness
                       int batch)
{
    __shared__ float s[RPB * NCLS];          // 41472 B
    __shared__ unsigned char smask[64];
    __shared__ float red[THREADS / 32];

    const int row0  = blockIdx.x * RPB;
    const int rows  = min(RPB, batch - row0);
    const int nflt  = rows * NCLS;

    // ---- stage logits chunk into smem, fully coalesced float4 ----
    const float* base = logits + (long long)row0 * NCLS;
    const int n4 = nflt >> 2;
    const float4* src4 = (const float4*)base;   // row0*54*4 bytes = 41472*blk -> 16B aligned
    float4* s4 = (float4*)s;
    for (int i = threadIdx.x; i < n4; i += THREADS) s4[i] = src4[i];
    for (int i = (n4 << 2) + threadIdx.x; i < nflt; i += THREADS) s[i] = base[i];
    if (threadIdx.x < NCLS) smask[threadIdx.x] = (unsigned char)(mask[threadIdx.x] != 0);
    __syncthreads();

    // ---- one row per thread ----
    float term = 0.0f;
    if (threadIdx.x < rows) {
        const float* x = s + threadIdx.x * NCLS;
        float r[NCLS];
        float m = -3.0e38f;
        int   am = 0;
        #pragma unroll
        for (int j = 0; j < NCLS; j++) {
            r[j] = x[j];
            if (r[j] > m) { m = r[j]; am = j; }   // strict '>' keeps first occurrence (jnp.argmax)
        }
        float sum = 0.0f;
        #pragma unroll
        for (int j = 0; j < NCLS; j++) sum += __expf(r[j] - m);

        const int t = target[row0 + threadIdx.x];
        const float xt = x[t];                     // dynamic index -> smem, not reg array
        const bool keep = (smask[am] | smask[t]) != 0;
        const float lse = m + __logf(sum);
        term = keep ? (lse - xt) : C0_TERM;
    }

    // ---- block reduction ----
    #pragma unroll
    for (int o = 16; o > 0; o >>= 1)
        term += __shfl_down_sync(0xffffffffu, term, o);
    const int lane = threadIdx.x & 31;
    const int w    = threadIdx.x >> 5;
    if (lane == 0) red[w] = term;
    __syncthreads();
    if (threadIdx.x == 0) {
        float bs = 0.0f;
        #pragma unroll
        for (int i = 0; i < THREADS / 32; i++) bs += red[i];
        atomicAdd(&g_acc, (double)bs);
    }
}

__global__ void finalize_kernel(float* out, int batch) {
    out[0] = (float)(g_acc / (double)batch);
}

extern "C" void kernel_launch(void* const* d_in, const int* in_sizes, int n_in,
                              void* d_out, int out_size)
{
    const float* logits = (const float*)d_in[0];
    const int*   target = (const int*)d_in[1];
    const int*   mask   = (const int*)d_in[2];
    float* out = (float*)d_out;

    const int batch = in_sizes[1];           // element count of target == B
    const int blocks = (batch + RPB - 1) / RPB;

    zero_acc_kernel<<<1, 1>>>();
    importance_loss_kernel<<<blocks, THREADS>>>(logits, target, mask, batch);
    finalize_kernel<<<1, 1>>>(out, batch);
}